// round 16
// baseline (speedup 1.0000x reference)
#include <cuda_runtime.h>
#include <cuda_fp16.h>
#include <cuda_bf16.h>
#include <math.h>

#define NN     50000
#define NE     800000
#define INCH   128
#define HH     256      // HEADS*HID
#define NHEAD  4
#define HID    64
#define GG     64
#define DCAT   640      // 128 + 256 + 256
#define NEG    0.2f

// ---------------- scratch (static device globals; no allocation) ----------------
__device__ __half g_lin16[(size_t)NN * HH];
__device__ __nv_bfloat16 g_xh[(size_t)NN * INCH];   // x split planes
__device__ __nv_bfloat16 g_xl[(size_t)NN * INCH];
__device__ __nv_bfloat16 g_h1h[(size_t)NN * HH];    // h1 planes (layer-1 output)
__device__ __nv_bfloat16 g_h1l[(size_t)NN * HH];
__device__ __nv_bfloat16 g_h2h[(size_t)NN * HH];    // h2 planes
__device__ __nv_bfloat16 g_h2l[(size_t)NN * HH];
__device__ float  g_esA[NN * NHEAD];
__device__ float  g_edA[NN * NHEAD];
__device__ float  g_esB[NN * NHEAD];
__device__ float  g_edB[NN * NHEAD];
__device__ unsigned g_gmaxA[NHEAD];
__device__ unsigned g_gmaxB[NHEAD];
__device__ int    g_deg[NN];
__device__ int    g_off[NN + 1];
__device__ int    g_cur[NN];
__device__ int    g_csr_src[NE];
__device__ float  g_pool[GG * DCAT];
__device__ float  g_cnt [GG];
__device__ __nv_bfloat16 g_wbh1[256 * 256];  // W1^T bf16 hi plane ([n][k])
__device__ __nv_bfloat16 g_wbl1[256 * 256];
__device__ __nv_bfloat16 g_wbh2[256 * 256];  // W2^T planes
__device__ __nv_bfloat16 g_wbl2[256 * 256];

// ---------------- helpers ----------------
__device__ __forceinline__ unsigned h2_as_u32(__half2 v) {
    unsigned r;
    memcpy(&r, &v, 4);
    return r;
}
__device__ __forceinline__ unsigned bf2_as_u32(__nv_bfloat16 a, __nv_bfloat16 b) {
    __nv_bfloat162 v = __halves2bfloat162(a, b);
    unsigned r;
    memcpy(&r, &v, 4);
    return r;
}
__device__ __forceinline__ float lrelu(float v) { return v > 0.f ? v : NEG * v; }

__device__ __forceinline__ void bf_split(float x, __nv_bfloat16& h, __nv_bfloat16& l) {
    h = __float2bfloat16(x);
    l = __float2bfloat16(x - __bfloat162float(h));
}

__device__ __forceinline__ unsigned f_enc(float f) {
    unsigned b = __float_as_uint(f);
    return (b & 0x80000000u) ? ~b : (b | 0x80000000u);
}
__device__ __forceinline__ float f_dec(unsigned u) {
    return (u & 0x80000000u) ? __uint_as_float(u ^ 0x80000000u) : __uint_as_float(~u);
}

__device__ __forceinline__ void mma_bf16(float& c0, float& c1, float& c2, float& c3,
                                         unsigned a0, unsigned a1, unsigned a2, unsigned a3,
                                         unsigned b0, unsigned b1) {
    asm volatile("mma.sync.aligned.m16n8k16.row.col.f32.bf16.bf16.f32 "
                 "{%0,%1,%2,%3},{%4,%5,%6,%7},{%8,%9},{%0,%1,%2,%3};"
                 : "+f"(c0), "+f"(c1), "+f"(c2), "+f"(c3)
                 : "r"(a0), "r"(a1), "r"(a2), "r"(a3), "r"(b0), "r"(b1));
}
__device__ __forceinline__ void ldsm_x4(unsigned& r0, unsigned& r1, unsigned& r2, unsigned& r3,
                                        unsigned addr) {
    asm volatile("ldmatrix.sync.aligned.m8n8.x4.shared.b16 {%0,%1,%2,%3}, [%4];"
                 : "=r"(r0), "=r"(r1), "=r"(r2), "=r"(r3) : "r"(addr));
}
__device__ __forceinline__ void ldsm_x2(unsigned& r0, unsigned& r1, unsigned addr) {
    asm volatile("ldmatrix.sync.aligned.m8n8.x2.shared.b16 {%0,%1}, [%2];"
                 : "=r"(r0), "=r"(r1) : "r"(addr));
}
__device__ __forceinline__ unsigned smem_u32(const void* p) {
    return (unsigned)__cvta_generic_to_shared(p);
}

// ---------------- setup kernels ----------------
__global__ void k_zero() {
    int i = blockIdx.x * blockDim.x + threadIdx.x;
    if (i < NN) {
        g_deg[i] = 0;
        float4 z = make_float4(0.f, 0.f, 0.f, 0.f);
        ((float4*)g_esA)[i] = z;
        ((float4*)g_edA)[i] = z;
        ((float4*)g_esB)[i] = z;
        ((float4*)g_edB)[i] = z;
    }
    if (i < GG * DCAT) g_pool[i] = 0.f;
    if (i < GG) g_cnt[i] = 0.f;
    if (i < NHEAD) { g_gmaxA[i] = 0u; g_gmaxB[i] = 0u; }
}

// split x into bf16 hi/lo planes (one float4 per thread)
__global__ void k_split_x(const float* __restrict__ x) {
    int i = blockIdx.x * blockDim.x + threadIdx.x;     // float4 index
    if (i >= NN * (INCH / 4)) return;
    float4 v = ((const float4*)x)[i];
    __nv_bfloat16 h0, l0, h1, l1, h2, l2, h3, l3;
    bf_split(v.x, h0, l0);
    bf_split(v.y, h1, l1);
    bf_split(v.z, h2, l2);
    bf_split(v.w, h3, l3);
    uint2 ph, pl;
    ph.x = bf2_as_u32(h0, h1); ph.y = bf2_as_u32(h2, h3);
    pl.x = bf2_as_u32(l0, l1); pl.y = bf2_as_u32(l2, l3);
    ((uint2*)g_xh)[i] = ph;
    ((uint2*)g_xl)[i] = pl;
}

// histogram of dst + per-graph node counts (fused)
__global__ void k_hist(const int* __restrict__ ei, const int* __restrict__ batch) {
    __shared__ float sh[GG];
    int t = threadIdx.x;
    if (t < GG) sh[t] = 0.f;
    __syncthreads();
    int i = blockIdx.x * blockDim.x + t;
    if (i < NE) atomicAdd(&g_deg[ei[NE + i]], 1);
    for (int n = i; n < NN; n += gridDim.x * blockDim.x)
        atomicAdd(&sh[batch[n]], 1.f);
    __syncthreads();
    if (t < GG) atomicAdd(&g_cnt[t], sh[t]);
}

__global__ void __launch_bounds__(1024) k_scan() {
    const int CH = (NN + 1023) / 1024;
    int t = threadIdx.x;
    int lane = t & 31, wid = t >> 5;
    int begin = t * CH;
    int end = min(begin + CH, NN);

    int s = 0;
    for (int i = begin; i < end; i++) s += g_deg[i];

    int v = s;
    #pragma unroll
    for (int o = 1; o < 32; o <<= 1) {
        int u = __shfl_up_sync(0xffffffffu, v, o);
        if (lane >= o) v += u;
    }
    __shared__ int wsum[32];
    if (lane == 31) wsum[wid] = v;
    __syncthreads();
    if (wid == 0) {
        int wv = wsum[lane];
        #pragma unroll
        for (int o = 1; o < 32; o <<= 1) {
            int u = __shfl_up_sync(0xffffffffu, wv, o);
            if (lane >= o) wv += u;
        }
        wsum[lane] = wv;
    }
    __syncthreads();
    int pre = v - s + (wid > 0 ? wsum[wid - 1] : 0);

    for (int i = begin; i < end; i++) {
        g_off[i] = pre;
        g_cur[i] = pre;
        pre += g_deg[i];
    }
    if (t == 1023) g_off[NN] = pre;
}

__global__ void k_scatter(const int* __restrict__ ei) {
    int e = blockIdx.x * blockDim.x + threadIdx.x;
    if (e < NE) {
        int s = ei[e];
        int d = ei[NE + e];
        int p = atomicAdd(&g_cur[d], 1);
        g_csr_src[p] = s;
    }
}

// ---------------- W transpose + bf16 split (both layers) ----------------
__global__ void k_split_w(const float* __restrict__ W1, const float* __restrict__ W2) {
    __shared__ float tile[32][33];
    int tx = threadIdx.x, ty = threadIdx.y;   // 32 x 8
    int which = blockIdx.z;
    if (which == 0 && blockIdx.y >= 4) return;
    const float* W = which ? W2 : W1;
    __nv_bfloat16* WH = which ? g_wbh2 : g_wbh1;
    __nv_bfloat16* WL = which ? g_wbl2 : g_wbl1;
    int n0 = blockIdx.x * 32, k0 = blockIdx.y * 32;
    for (int i = ty; i < 32; i += 8)
        tile[i][tx] = W[(size_t)(k0 + i) * 256 + n0 + tx];
    __syncthreads();
    for (int i = ty; i < 32; i += 8) {
        float v = tile[tx][i];
        __nv_bfloat16 h, l;
        bf_split(v, h, l);
        WH[(size_t)(n0 + i) * 256 + k0 + tx] = h;
        WL[(size_t)(n0 + i) * 256 + k0 + tx] = l;
    }
}

// ---------------- bf16x3 GEMM (plane inputs) + fused logits/fp16 epilogue ----------------
#define KP 72
#define KCB 64

template<int K>
__global__ void __launch_bounds__(256, 2) k_gemm_tc(const __nv_bfloat16* __restrict__ AH,
                                                    const __nv_bfloat16* __restrict__ AL,
                                                    const __nv_bfloat16* __restrict__ WHp,
                                                    const __nv_bfloat16* __restrict__ WLp,
                                                    __half* __restrict__ out16,
                                                    const float* __restrict__ asrc,
                                                    const float* __restrict__ adst,
                                                    float* __restrict__ es,
                                                    float* __restrict__ ed) {
    extern __shared__ __nv_bfloat16 smem[];
    __nv_bfloat16* Xh = smem;
    __nv_bfloat16* Xl = smem + 64 * KP;
    __nv_bfloat16* Wh = smem + 2 * 64 * KP;
    __nv_bfloat16* Wl = smem + 2 * 64 * KP + 128 * KP;

    int t = threadIdx.x;
    int lane = t & 31, wid = t >> 5;
    int warp_m = wid >> 2;
    int warp_n = wid & 3;
    int rowbase = blockIdx.x * 64;
    int ctacol = blockIdx.y * 128;

    float c[2][4][4];
    #pragma unroll
    for (int mf = 0; mf < 2; mf++)
        #pragma unroll
        for (int nf = 0; nf < 4; nf++)
            #pragma unroll
            for (int i = 0; i < 4; i++) c[mf][nf][i] = 0.f;

    unsigned xh_u = smem_u32(Xh), xl_u = smem_u32(Xl);
    unsigned wh_u = smem_u32(Wh), wl_u = smem_u32(Wl);
    unsigned aoffs = 2u * ((warp_m * 32 + (lane & 15)) * KP + ((lane >> 4) & 1) * 8);
    unsigned boffs = 2u * ((warp_n * 32 + (lane & 7)) * KP + ((lane >> 3) & 1) * 8);

    const uint4 z4 = make_uint4(0u, 0u, 0u, 0u);

    for (int kc = 0; kc < K; kc += KCB) {
        // A planes: 64 rows x 64 k = 8 uint4 per row per plane (pure copy)
        #pragma unroll
        for (int it = 0; it < 2; it++) {
            int item = t + it * 256;          // 0..511
            int r = item >> 3, j = item & 7;
            int gr = rowbase + r;
            uint4 v = z4;
            if (gr < NN) v = *(const uint4*)(AH + (size_t)gr * K + kc + j * 8);
            *(uint4*)(Xh + r * KP + j * 8) = v;
        }
        #pragma unroll
        for (int it = 0; it < 2; it++) {
            int item = t + it * 256;
            int r = item >> 3, j = item & 7;
            int gr = rowbase + r;
            uint4 v = z4;
            if (gr < NN) v = *(const uint4*)(AL + (size_t)gr * K + kc + j * 8);
            *(uint4*)(Xl + r * KP + j * 8) = v;
        }
        // W planes: 128 n x 64 k = 8 uint4 per n per plane
        #pragma unroll
        for (int it = 0; it < 4; it++) {
            int item = t + it * 256;
            int n = item >> 3, j = item & 7;
            const uint4* srcH = (const uint4*)(WHp + (size_t)(ctacol + n) * 256 + kc);
            *(uint4*)(Wh + n * KP + j * 8) = srcH[j];
        }
        #pragma unroll
        for (int it = 0; it < 4; it++) {
            int item = t + it * 256;
            int n = item >> 3, j = item & 7;
            const uint4* srcL = (const uint4*)(WLp + (size_t)(ctacol + n) * 256 + kc);
            *(uint4*)(Wl + n * KP + j * 8) = srcL[j];
        }
        __syncthreads();

        #pragma unroll
        for (int ks = 0; ks < KCB / 16; ks++) {
            unsigned kbb = (unsigned)(ks * 16) * 2u;
            unsigned ah[2][4], al[2][4];
            #pragma unroll
            for (int mf = 0; mf < 2; mf++) {
                unsigned mo = (unsigned)(mf * 16 * KP) * 2u;
                ldsm_x4(ah[mf][0], ah[mf][1], ah[mf][2], ah[mf][3], xh_u + aoffs + mo + kbb);
                ldsm_x4(al[mf][0], al[mf][1], al[mf][2], al[mf][3], xl_u + aoffs + mo + kbb);
            }
            #pragma unroll
            for (int nf = 0; nf < 4; nf++) {
                unsigned no = (unsigned)(nf * 8 * KP) * 2u;
                unsigned bh0, bh1, bl0, bl1;
                ldsm_x2(bh0, bh1, wh_u + boffs + no + kbb);
                ldsm_x2(bl0, bl1, wl_u + boffs + no + kbb);
                #pragma unroll
                for (int mf = 0; mf < 2; mf++) {
                    float* cc = c[mf][nf];
                    mma_bf16(cc[0], cc[1], cc[2], cc[3],
                             ah[mf][0], ah[mf][1], ah[mf][2], ah[mf][3], bh0, bh1);
                    mma_bf16(cc[0], cc[1], cc[2], cc[3],
                             ah[mf][0], ah[mf][1], ah[mf][2], ah[mf][3], bl0, bl1);
                    mma_bf16(cc[0], cc[1], cc[2], cc[3],
                             al[mf][0], al[mf][1], al[mf][2], al[mf][3], bh0, bh1);
                }
            }
        }
        __syncthreads();
    }

    // ---- epilogue: fp16 store + fused logits ----
    int head = (ctacol >> 6) + (warp_n >> 1);
    #pragma unroll
    for (int mf = 0; mf < 2; mf++) {
        int r0 = rowbase + warp_m * 32 + mf * 16 + (lane >> 2);
        int r1 = r0 + 8;
        float pes0 = 0.f, ped0 = 0.f, pes1 = 0.f, ped1 = 0.f;
        #pragma unroll
        for (int nf = 0; nf < 4; nf++) {
            int col = ctacol + warp_n * 32 + nf * 8 + (lane & 3) * 2;
            float av0 = __ldg(asrc + col), av1 = __ldg(asrc + col + 1);
            float dv0 = __ldg(adst + col), dv1 = __ldg(adst + col + 1);
            float* cc = c[mf][nf];
            pes0 += cc[0] * av0 + cc[1] * av1;
            ped0 += cc[0] * dv0 + cc[1] * dv1;
            pes1 += cc[2] * av0 + cc[3] * av1;
            ped1 += cc[2] * dv0 + cc[3] * dv1;
            if (r0 < NN)
                *(unsigned*)(out16 + (size_t)r0 * HH + col) = h2_as_u32(__floats2half2_rn(cc[0], cc[1]));
            if (r1 < NN)
                *(unsigned*)(out16 + (size_t)r1 * HH + col) = h2_as_u32(__floats2half2_rn(cc[2], cc[3]));
        }
        pes0 += __shfl_xor_sync(0xffffffffu, pes0, 1);
        pes0 += __shfl_xor_sync(0xffffffffu, pes0, 2);
        ped0 += __shfl_xor_sync(0xffffffffu, ped0, 1);
        ped0 += __shfl_xor_sync(0xffffffffu, ped0, 2);
        pes1 += __shfl_xor_sync(0xffffffffu, pes1, 1);
        pes1 += __shfl_xor_sync(0xffffffffu, pes1, 2);
        ped1 += __shfl_xor_sync(0xffffffffu, ped1, 1);
        ped1 += __shfl_xor_sync(0xffffffffu, ped1, 2);
        if ((lane & 3) == 0) {
            if (r0 < NN) {
                atomicAdd(&es[r0 * NHEAD + head], pes0);
                atomicAdd(&ed[r0 * NHEAD + head], ped0);
            }
            if (r1 < NN) {
                atomicAdd(&es[r1 * NHEAD + head], pes1);
                atomicAdd(&ed[r1 * NHEAD + head], ped1);
            }
        }
    }
}

// ---------------- per-head global max of es ----------------
__global__ void k_gmax(const float* __restrict__ es, unsigned* __restrict__ gmax) {
    __shared__ unsigned sm[NHEAD];
    int t = threadIdx.x;
    if (t < NHEAD) sm[t] = 0u;
    __syncthreads();
    float m0 = -1e30f, m1 = -1e30f, m2 = -1e30f, m3 = -1e30f;
    for (int n = blockIdx.x * blockDim.x + t; n < NN; n += gridDim.x * blockDim.x) {
        float4 v = ((const float4*)es)[n];
        m0 = fmaxf(m0, v.x); m1 = fmaxf(m1, v.y);
        m2 = fmaxf(m2, v.z); m3 = fmaxf(m3, v.w);
    }
    atomicMax(&sm[0], f_enc(m0));
    atomicMax(&sm[1], f_enc(m1));
    atomicMax(&sm[2], f_enc(m2));
    atomicMax(&sm[3], f_enc(m3));
    __syncthreads();
    if (t < NHEAD) atomicMax(&gmax[t], sm[t]);
}

// ---------------- aggregation: warp per dst node, bf16-plane output ----------------
__global__ void __launch_bounds__(256) k_agg(const __half* __restrict__ lin16,
                                             const float* __restrict__ bias,
                                             __nv_bfloat16* __restrict__ outH,
                                             __nv_bfloat16* __restrict__ outL,
                                             const float* __restrict__ es,
                                             const float* __restrict__ ed,
                                             const unsigned* __restrict__ gmax) {
    int n = (blockIdx.x * blockDim.x + threadIdx.x) >> 5;
    if (n >= NN) return;
    int lane = threadIdx.x & 31;

    int e0 = g_off[n], e1 = g_off[n + 1];
    float4 edv = ((const float4*)ed)[n];
    int head = lane >> 3;
    float edme = (head == 0) ? edv.x : (head == 1) ? edv.y : (head == 2) ? edv.z : edv.w;
    float mh = fmaxf(0.f, f_dec(__ldg(&gmax[head])) + edme);

    float a0=0,a1=0,a2=0,a3=0,a4=0,a5=0,a6=0,a7=0, den=0;
    const uint4* lp = (const uint4*)lin16;

    int e = e0;
    for (; e + 3 < e1; e += 4) {
        int s0 = g_csr_src[e];
        int s1 = g_csr_src[e + 1];
        int s2 = g_csr_src[e + 2];
        int s3 = g_csr_src[e + 3];
        float ex0 = __expf(lrelu(es[s0 * NHEAD + head] + edme) - mh);
        float ex1 = __expf(lrelu(es[s1 * NHEAD + head] + edme) - mh);
        float ex2 = __expf(lrelu(es[s2 * NHEAD + head] + edme) - mh);
        float ex3 = __expf(lrelu(es[s3 * NHEAD + head] + edme) - mh);
        uint4 r0 = lp[(size_t)s0 * 32 + lane];
        uint4 r1 = lp[(size_t)s1 * 32 + lane];
        uint4 r2 = lp[(size_t)s2 * 32 + lane];
        uint4 r3 = lp[(size_t)s3 * 32 + lane];
        den += (ex0 + ex1) + (ex2 + ex3);
        {
            float2 f0 = __half22float2(*(__half2*)&r0.x);
            float2 f1 = __half22float2(*(__half2*)&r0.y);
            float2 f2 = __half22float2(*(__half2*)&r0.z);
            float2 f3 = __half22float2(*(__half2*)&r0.w);
            a0 += ex0 * f0.x; a1 += ex0 * f0.y; a2 += ex0 * f1.x; a3 += ex0 * f1.y;
            a4 += ex0 * f2.x; a5 += ex0 * f2.y; a6 += ex0 * f3.x; a7 += ex0 * f3.y;
        }
        {
            float2 f0 = __half22float2(*(__half2*)&r1.x);
            float2 f1 = __half22float2(*(__half2*)&r1.y);
            float2 f2 = __half22float2(*(__half2*)&r1.z);
            float2 f3 = __half22float2(*(__half2*)&r1.w);
            a0 += ex1 * f0.x; a1 += ex1 * f0.y; a2 += ex1 * f1.x; a3 += ex1 * f1.y;
            a4 += ex1 * f2.x; a5 += ex1 * f2.y; a6 += ex1 * f3.x; a7 += ex1 * f3.y;
        }
        {
            float2 f0 = __half22float2(*(__half2*)&r2.x);
            float2 f1 = __half22float2(*(__half2*)&r2.y);
            float2 f2 = __half22float2(*(__half2*)&r2.z);
            float2 f3 = __half22float2(*(__half2*)&r2.w);
            a0 += ex2 * f0.x; a1 += ex2 * f0.y; a2 += ex2 * f1.x; a3 += ex2 * f1.y;
            a4 += ex2 * f2.x; a5 += ex2 * f2.y; a6 += ex2 * f3.x; a7 += ex2 * f3.y;
        }
        {
            float2 f0 = __half22float2(*(__half2*)&r3.x);
            float2 f1 = __half22float2(*(__half2*)&r3.y);
            float2 f2 = __half22float2(*(__half2*)&r3.z);
            float2 f3 = __half22float2(*(__half2*)&r3.w);
            a0 += ex3 * f0.x; a1 += ex3 * f0.y; a2 += ex3 * f1.x; a3 += ex3 * f1.y;
            a4 += ex3 * f2.x; a5 += ex3 * f2.y; a6 += ex3 * f3.x; a7 += ex3 * f3.y;
        }
    }
    for (; e < e1; e++) {
        int s0 = g_csr_src[e];
        float ex0 = __expf(lrelu(es[s0 * NHEAD + head] + edme) - mh);
        uint4 r0 = lp[(size_t)s0 * 32 + lane];
        den += ex0;
        float2 f0 = __half22float2(*(__half2*)&r0.x);
        float2 f1 = __half22float2(*(__half2*)&r0.y);
        float2 f2 = __half22float2(*(__half2*)&r0.z);
        float2 f3 = __half22float2(*(__half2*)&r0.w);
        a0 += ex0 * f0.x; a1 += ex0 * f0.y; a2 += ex0 * f1.x; a3 += ex0 * f1.y;
        a4 += ex0 * f2.x; a5 += ex0 * f2.y; a6 += ex0 * f3.x; a7 += ex0 * f3.y;
    }

    float inv = 1.f / (den + 1e-16f);
    const float4* bv = (const float4*)(bias + lane * 8);
    float4 bb0 = __ldg(&bv[0]), bb1 = __ldg(&bv[1]);
    float o[8];
    o[0] = fmaxf(a0 * inv + bb0.x, 0.f);
    o[1] = fmaxf(a1 * inv + bb0.y, 0.f);
    o[2] = fmaxf(a2 * inv + bb0.z, 0.f);
    o[3] = fmaxf(a3 * inv + bb0.w, 0.f);
    o[4] = fmaxf(a4 * inv + bb1.x, 0.f);
    o[5] = fmaxf(a5 * inv + bb1.y, 0.f);
    o[6] = fmaxf(a6 * inv + bb1.z, 0.f);
    o[7] = fmaxf(a7 * inv + bb1.w, 0.f);

    __nv_bfloat16 hh[8], ll[8];
    #pragma unroll
    for (int i = 0; i < 8; i++) bf_split(o[i], hh[i], ll[i]);
    uint4 oh, ol;
    oh.x = bf2_as_u32(hh[0], hh[1]); oh.y = bf2_as_u32(hh[2], hh[3]);
    oh.z = bf2_as_u32(hh[4], hh[5]); oh.w = bf2_as_u32(hh[6], hh[7]);
    ol.x = bf2_as_u32(ll[0], ll[1]); ol.y = bf2_as_u32(ll[2], ll[3]);
    ol.z = bf2_as_u32(ll[4], ll[5]); ol.w = bf2_as_u32(ll[6], ll[7]);
    ((uint4*)(outH + (size_t)n * HH))[lane] = oh;
    ((uint4*)(outL + (size_t)n * HH))[lane] = ol;
}

// ---------------- pooling (reads bf16 planes for h1/h2) ----------------
__global__ void __launch_bounds__(640) k_pool(const float* __restrict__ x,
                                              const int* __restrict__ batch) {
    __shared__ int bsh[256];
    int t = threadIdx.x;
    int n0 = blockIdx.x * 256;
    int cnt = min(256, NN - n0);
    for (int i = t; i < cnt; i += 640) bsh[i] = batch[n0 + i];
    __syncthreads();

    const __nv_bfloat16 *hb = 0, *lb = 0;
    const float* xb = 0;
    int coff;
    if (t < 128)      { xb = x; coff = t; }
    else if (t < 384) { hb = g_h1h; lb = g_h1l; coff = t - 128; }
    else              { hb = g_h2h; lb = g_h2l; coff = t - 384; }

    float acc = 0.f;
    int curg = bsh[0];
    #pragma unroll 4
    for (int i = 0; i < cnt; i++) {
        int g = bsh[i];
        float v;
        if (xb) v = xb[(size_t)(n0 + i) * INCH + coff];
        else    v = __bfloat162float(hb[(size_t)(n0 + i) * HH + coff])
                  + __bfloat162float(lb[(size_t)(n0 + i) * HH + coff]);
        if (g != curg) {
            atomicAdd(&g_pool[curg * DCAT + t], acc);
            acc = 0.f;
            curg = g;
        }
        acc += v;
    }
    atomicAdd(&g_pool[curg * DCAT + t], acc);
}

// ---------------- final MLP ----------------
__global__ void k_mlp(const float* __restrict__ W3, const float* __restrict__ b3,
                      const float* __restrict__ W4, const float* __restrict__ b4,
                      float* __restrict__ out) {
    int g = blockIdx.x;
    int t = threadIdx.x;
    __shared__ float p[DCAT];
    __shared__ float hm[256];
    float invc = 1.f / fmaxf(g_cnt[g], 1.f);
    for (int i = t; i < DCAT; i += 256) p[i] = g_pool[g * DCAT + i] * invc;
    __syncthreads();
    float acc = b3[t];
    for (int k = 0; k < DCAT; k++) acc += p[k] * W3[k * 256 + t];
    hm[t] = fmaxf(acc, 0.f);
    __syncthreads();
    if (t < 128) {
        float a2 = b4[t];
        for (int k = 0; k < 256; k++) a2 += hm[k] * W4[k * 128 + t];
        out[g * 128 + t] = a2;
    }
}

// ---------------- launch ----------------
extern "C" void kernel_launch(void* const* d_in, const int* in_sizes, int n_in,
                              void* d_out, int out_size) {
    const float* x     = (const float*)d_in[0];
    const int*   ei    = (const int*)d_in[1];
    const int*   batch = (const int*)d_in[2];
    const float* W1  = (const float*)d_in[3];
    const float* a1s = (const float*)d_in[4];
    const float* a1d = (const float*)d_in[5];
    const float* b1  = (const float*)d_in[6];
    const float* W2  = (const float*)d_in[7];
    const float* a2s = (const float*)d_in[8];
    const float* a2d = (const float*)d_in[9];
    const float* b2  = (const float*)d_in[10];
    const float* W3  = (const float*)d_in[11];
    const float* b3  = (const float*)d_in[12];
    const float* W4  = (const float*)d_in[13];
    const float* b4  = (const float*)d_in[14];
    float* out = (float*)d_out;

    void *p_l16, *p_xh, *p_xl, *p_h1h, *p_h1l, *p_h2h, *p_h2l;
    void *p_esA, *p_edA, *p_esB, *p_edB, *p_gmA, *p_gmB;
    void *p_wh1, *p_wl1, *p_wh2, *p_wl2;
    cudaGetSymbolAddress(&p_l16, g_lin16);
    cudaGetSymbolAddress(&p_xh,  g_xh);
    cudaGetSymbolAddress(&p_xl,  g_xl);
    cudaGetSymbolAddress(&p_h1h, g_h1h);
    cudaGetSymbolAddress(&p_h1l, g_h1l);
    cudaGetSymbolAddress(&p_h2h, g_h2h);
    cudaGetSymbolAddress(&p_h2l, g_h2l);
    cudaGetSymbolAddress(&p_esA, g_esA);
    cudaGetSymbolAddress(&p_edA, g_edA);
    cudaGetSymbolAddress(&p_esB, g_esB);
    cudaGetSymbolAddress(&p_edB, g_edB);
    cudaGetSymbolAddress(&p_gmA, g_gmaxA);
    cudaGetSymbolAddress(&p_gmB, g_gmaxB);
    cudaGetSymbolAddress(&p_wh1, g_wbh1);
    cudaGetSymbolAddress(&p_wl1, g_wbl1);
    cudaGetSymbolAddress(&p_wh2, g_wbh2);
    cudaGetSymbolAddress(&p_wl2, g_wbl2);
    __half* lin16 = (__half*)p_l16;

    const int SMEM_GEMM = (2 * 64 * KP + 2 * 128 * KP) * sizeof(__nv_bfloat16);  // 55,296 B
    cudaFuncSetAttribute(k_gemm_tc<128>, cudaFuncAttributeMaxDynamicSharedMemorySize, SMEM_GEMM);
    cudaFuncSetAttribute(k_gemm_tc<256>, cudaFuncAttributeMaxDynamicSharedMemorySize, SMEM_GEMM);

    dim3 gemm_grid((NN + 63) / 64, 2);
    int warp_blocks = (NN * 32 + 255) / 256;
    dim3 tb(32, 8);

    // slot 4 = gemm<128> (profiled)
    k_split_x<<<(NN * (INCH / 4) + 255) / 256, 256>>>(x);          // 1
    k_split_w<<<dim3(8, 8, 2), tb>>>(W1, W2);                      // 2
    k_zero<<<(NN + 255) / 256, 256>>>();                           // 3
    k_gemm_tc<128><<<gemm_grid, 256, SMEM_GEMM>>>(                 // 4 <- profiled
        (__nv_bfloat16*)p_xh, (__nv_bfloat16*)p_xl,
        (__nv_bfloat16*)p_wh1, (__nv_bfloat16*)p_wl1,
        lin16, a1s, a1d, (float*)p_esA, (float*)p_edA);
    k_hist<<<(NE + 255) / 256, 256>>>(ei, batch);                  // 5
    k_scan<<<1, 1024>>>();                                         // 6
    k_scatter<<<(NE + 255) / 256, 256>>>(ei);                      // 7
    k_gmax<<<160, 256>>>((const float*)p_esA, (unsigned*)p_gmA);   // 8

    k_agg<<<warp_blocks, 256>>>(lin16, b1,
        (__nv_bfloat16*)p_h1h, (__nv_bfloat16*)p_h1l,
        (const float*)p_esA, (const float*)p_edA, (const unsigned*)p_gmA);

    k_gemm_tc<256><<<gemm_grid, 256, SMEM_GEMM>>>(
        (__nv_bfloat16*)p_h1h, (__nv_bfloat16*)p_h1l,
        (__nv_bfloat16*)p_wh2, (__nv_bfloat16*)p_wl2,
        lin16, a2s, a2d, (float*)p_esB, (float*)p_edB);
    k_gmax<<<160, 256>>>((const float*)p_esB, (unsigned*)p_gmB);
    k_agg<<<warp_blocks, 256>>>(lin16, b2,
        (__nv_bfloat16*)p_h2h, (__nv_bfloat16*)p_h2l,
        (const float*)p_esB, (const float*)p_edB, (const unsigned*)p_gmB);

    k_pool<<<(NN + 255) / 256, 640>>>(x, batch);
    k_mlp<<<GG, 256>>>(W3, b3, W4, b4, out);
}

// round 17
// speedup vs baseline: 1.3420x; 1.3420x over previous
#include <cuda_runtime.h>
#include <cuda_fp16.h>
#include <cuda_bf16.h>
#include <math.h>

#define NN     50000
#define NE     800000
#define INCH   128
#define HH     256      // HEADS*HID
#define NHEAD  4
#define HID    64
#define GG     64
#define DCAT   640      // 128 + 256 + 256
#define NEG    0.2f

// ---------------- scratch (static device globals; no allocation) ----------------
__device__ __half g_lin16[(size_t)NN * HH];
__device__ float  g_h1 [(size_t)NN * HH];
__device__ float  g_h2 [(size_t)NN * HH];
__device__ float  g_esA[NN * NHEAD];
__device__ float  g_edA[NN * NHEAD];
__device__ float  g_esB[NN * NHEAD];
__device__ float  g_edB[NN * NHEAD];
__device__ unsigned g_gmaxA[NHEAD];
__device__ unsigned g_gmaxB[NHEAD];
__device__ int    g_deg[NN];
__device__ int    g_off[NN + 1];
__device__ int    g_cur[NN];
__device__ int    g_csr_src[NE];
__device__ float  g_pool[GG * DCAT];
__device__ float  g_cnt [GG];
__device__ __nv_bfloat16 g_wbh1[256 * 256];  // W1^T bf16 hi plane ([n][k])
__device__ __nv_bfloat16 g_wbl1[256 * 256];
__device__ __nv_bfloat16 g_wbh2[256 * 256];  // W2^T planes
__device__ __nv_bfloat16 g_wbl2[256 * 256];

// ---------------- helpers ----------------
__device__ __forceinline__ unsigned h2_as_u32(__half2 v) {
    unsigned r;
    memcpy(&r, &v, 4);
    return r;
}
__device__ __forceinline__ unsigned bf2_as_u32(__nv_bfloat16 a, __nv_bfloat16 b) {
    __nv_bfloat162 v = __halves2bfloat162(a, b);
    unsigned r;
    memcpy(&r, &v, 4);
    return r;
}
__device__ __forceinline__ float lrelu(float v) { return v > 0.f ? v : NEG * v; }

__device__ __forceinline__ void bf_split(float x, __nv_bfloat16& h, __nv_bfloat16& l) {
    h = __float2bfloat16(x);
    l = __float2bfloat16(x - __bfloat162float(h));
}

__device__ __forceinline__ unsigned f_enc(float f) {
    unsigned b = __float_as_uint(f);
    return (b & 0x80000000u) ? ~b : (b | 0x80000000u);
}
__device__ __forceinline__ float f_dec(unsigned u) {
    return (u & 0x80000000u) ? __uint_as_float(u ^ 0x80000000u) : __uint_as_float(~u);
}

__device__ __forceinline__ void mma_bf16(float& c0, float& c1, float& c2, float& c3,
                                         unsigned a0, unsigned a1, unsigned a2, unsigned a3,
                                         unsigned b0, unsigned b1) {
    asm volatile("mma.sync.aligned.m16n8k16.row.col.f32.bf16.bf16.f32 "
                 "{%0,%1,%2,%3},{%4,%5,%6,%7},{%8,%9},{%0,%1,%2,%3};"
                 : "+f"(c0), "+f"(c1), "+f"(c2), "+f"(c3)
                 : "r"(a0), "r"(a1), "r"(a2), "r"(a3), "r"(b0), "r"(b1));
}
__device__ __forceinline__ void ldsm_x4(unsigned& r0, unsigned& r1, unsigned& r2, unsigned& r3,
                                        unsigned addr) {
    asm volatile("ldmatrix.sync.aligned.m8n8.x4.shared.b16 {%0,%1,%2,%3}, [%4];"
                 : "=r"(r0), "=r"(r1), "=r"(r2), "=r"(r3) : "r"(addr));
}
__device__ __forceinline__ unsigned smem_u32(const void* p) {
    return (unsigned)__cvta_generic_to_shared(p);
}

// ---------------- setup kernels ----------------
__global__ void k_zero() {
    int i = blockIdx.x * blockDim.x + threadIdx.x;
    if (i < NN) {
        g_deg[i] = 0;
        float4 z = make_float4(0.f, 0.f, 0.f, 0.f);
        ((float4*)g_esA)[i] = z;
        ((float4*)g_edA)[i] = z;
        ((float4*)g_esB)[i] = z;
        ((float4*)g_edB)[i] = z;
    }
    if (i < GG * DCAT) g_pool[i] = 0.f;
    if (i < GG) g_cnt[i] = 0.f;
    if (i < NHEAD) { g_gmaxA[i] = 0u; g_gmaxB[i] = 0u; }
}

// histogram of dst + per-graph node counts (fused)
__global__ void k_hist(const int* __restrict__ ei, const int* __restrict__ batch) {
    __shared__ float sh[GG];
    int t = threadIdx.x;
    if (t < GG) sh[t] = 0.f;
    __syncthreads();
    int i = blockIdx.x * blockDim.x + t;
    if (i < NE) atomicAdd(&g_deg[ei[NE + i]], 1);
    for (int n = i; n < NN; n += gridDim.x * blockDim.x)
        atomicAdd(&sh[batch[n]], 1.f);
    __syncthreads();
    if (t < GG) atomicAdd(&g_cnt[t], sh[t]);
}

__global__ void __launch_bounds__(1024) k_scan() {
    const int CH = (NN + 1023) / 1024;
    int t = threadIdx.x;
    int lane = t & 31, wid = t >> 5;
    int begin = t * CH;
    int end = min(begin + CH, NN);

    int s = 0;
    for (int i = begin; i < end; i++) s += g_deg[i];

    int v = s;
    #pragma unroll
    for (int o = 1; o < 32; o <<= 1) {
        int u = __shfl_up_sync(0xffffffffu, v, o);
        if (lane >= o) v += u;
    }
    __shared__ int wsum[32];
    if (lane == 31) wsum[wid] = v;
    __syncthreads();
    if (wid == 0) {
        int wv = wsum[lane];
        #pragma unroll
        for (int o = 1; o < 32; o <<= 1) {
            int u = __shfl_up_sync(0xffffffffu, wv, o);
            if (lane >= o) wv += u;
        }
        wsum[lane] = wv;
    }
    __syncthreads();
    int pre = v - s + (wid > 0 ? wsum[wid - 1] : 0);

    for (int i = begin; i < end; i++) {
        g_off[i] = pre;
        g_cur[i] = pre;
        pre += g_deg[i];
    }
    if (t == 1023) g_off[NN] = pre;
}

__global__ void k_scatter(const int* __restrict__ ei) {
    int e = blockIdx.x * blockDim.x + threadIdx.x;
    if (e < NE) {
        int s = ei[e];
        int d = ei[NE + e];
        int p = atomicAdd(&g_cur[d], 1);
        g_csr_src[p] = s;
    }
}

// ---------------- W transpose + bf16 split (both layers) ----------------
__global__ void k_split_w(const float* __restrict__ W1, const float* __restrict__ W2) {
    __shared__ float tile[32][33];
    int tx = threadIdx.x, ty = threadIdx.y;   // 32 x 8
    int which = blockIdx.z;
    if (which == 0 && blockIdx.y >= 4) return;
    const float* W = which ? W2 : W1;
    __nv_bfloat16* WH = which ? g_wbh2 : g_wbh1;
    __nv_bfloat16* WL = which ? g_wbl2 : g_wbl1;
    int n0 = blockIdx.x * 32, k0 = blockIdx.y * 32;
    for (int i = ty; i < 32; i += 8)
        tile[i][tx] = W[(size_t)(k0 + i) * 256 + n0 + tx];
    __syncthreads();
    for (int i = ty; i < 32; i += 8) {
        float v = tile[tx][i];
        __nv_bfloat16 h, l;
        bf_split(v, h, l);
        WH[(size_t)(n0 + i) * 256 + k0 + tx] = h;
        WL[(size_t)(n0 + i) * 256 + k0 + tx] = l;
    }
}

// ---------------- bf16x3 GEMM + fused logits/fp16 epilogue (ldmatrix x4 loads) ----------------
#define KP 72
#define KCB 64

template<int K>
__global__ void __launch_bounds__(256, 2) k_gemm_tc(const float* __restrict__ X,
                                                    const __nv_bfloat16* __restrict__ WHp,
                                                    const __nv_bfloat16* __restrict__ WLp,
                                                    __half* __restrict__ out16,
                                                    const float* __restrict__ asrc,
                                                    const float* __restrict__ adst,
                                                    float* __restrict__ es,
                                                    float* __restrict__ ed) {
    extern __shared__ __nv_bfloat16 smem[];
    __nv_bfloat16* Xh = smem;
    __nv_bfloat16* Xl = smem + 64 * KP;
    __nv_bfloat16* Wh = smem + 2 * 64 * KP;
    __nv_bfloat16* Wl = smem + 2 * 64 * KP + 128 * KP;

    int t = threadIdx.x;
    int lane = t & 31, wid = t >> 5;
    int warp_m = wid >> 2;
    int warp_n = wid & 3;
    int rowbase = blockIdx.x * 64;
    int ctacol = blockIdx.y * 128;

    float c[2][4][4];
    #pragma unroll
    for (int mf = 0; mf < 2; mf++)
        #pragma unroll
        for (int nf = 0; nf < 4; nf++)
            #pragma unroll
            for (int i = 0; i < 4; i++) c[mf][nf][i] = 0.f;

    const float4* Xv = (const float4*)X;

    unsigned xh_u = smem_u32(Xh), xl_u = smem_u32(Xl);
    unsigned wh_u = smem_u32(Wh), wl_u = smem_u32(Wl);
    unsigned aoffs = 2u * ((warp_m * 32 + (lane & 15)) * KP + ((lane >> 4) & 1) * 8);
    // B x4 pairing: lanes 0-7 -> nf rows k0, 8-15 -> nf k8, 16-23 -> nf+1 k0, 24-31 -> nf+1 k8
    unsigned boffs = 2u * ((warp_n * 32 + ((lane >> 4) & 1) * 8 + (lane & 7)) * KP
                          + ((lane >> 3) & 1) * 8);

    for (int kc = 0; kc < K; kc += KCB) {
        #pragma unroll
        for (int it = 0; it < 4; it++) {
            int item = t + it * 256;
            int r = item >> 4, j = item & 15;
            int gr = rowbase + r;
            float4 v = make_float4(0.f, 0.f, 0.f, 0.f);
            if (gr < NN) v = Xv[(size_t)gr * (K / 4) + (kc >> 2) + j];
            __nv_bfloat16 h0, l0, h1, l1, h2, l2, h3, l3;
            bf_split(v.x, h0, l0);
            bf_split(v.y, h1, l1);
            bf_split(v.z, h2, l2);
            bf_split(v.w, h3, l3);
            uint2 ph, pl;
            ph.x = bf2_as_u32(h0, h1); ph.y = bf2_as_u32(h2, h3);
            pl.x = bf2_as_u32(l0, l1); pl.y = bf2_as_u32(l2, l3);
            *(uint2*)(Xh + r * KP + j * 4) = ph;
            *(uint2*)(Xl + r * KP + j * 4) = pl;
        }
        #pragma unroll
        for (int it = 0; it < 4; it++) {
            int item = t + it * 256;
            int n = item >> 3, j = item & 7;
            const uint4* srcH = (const uint4*)(WHp + (size_t)(ctacol + n) * 256 + kc);
            *(uint4*)(Wh + n * KP + j * 8) = srcH[j];
        }
        #pragma unroll
        for (int it = 0; it < 4; it++) {
            int item = t + it * 256;
            int n = item >> 3, j = item & 7;
            const uint4* srcL = (const uint4*)(WLp + (size_t)(ctacol + n) * 256 + kc);
            *(uint4*)(Wl + n * KP + j * 8) = srcL[j];
        }
        __syncthreads();

        #pragma unroll
        for (int ks = 0; ks < KCB / 16; ks++) {
            unsigned kbb = (unsigned)(ks * 16) * 2u;
            unsigned ah[2][4], al[2][4];
            #pragma unroll
            for (int mf = 0; mf < 2; mf++) {
                unsigned mo = (unsigned)(mf * 16 * KP) * 2u;
                ldsm_x4(ah[mf][0], ah[mf][1], ah[mf][2], ah[mf][3], xh_u + aoffs + mo + kbb);
                ldsm_x4(al[mf][0], al[mf][1], al[mf][2], al[mf][3], xl_u + aoffs + mo + kbb);
            }
            #pragma unroll
            for (int p = 0; p < 2; p++) {
                unsigned po = (unsigned)(p * 16 * KP) * 2u;   // pair covers nf=2p, 2p+1
                unsigned bh0, bh1, bh2, bh3, bl0, bl1, bl2, bl3;
                ldsm_x4(bh0, bh1, bh2, bh3, wh_u + boffs + po + kbb);
                ldsm_x4(bl0, bl1, bl2, bl3, wl_u + boffs + po + kbb);
                #pragma unroll
                for (int mf = 0; mf < 2; mf++) {
                    float* c0 = c[mf][2 * p];
                    mma_bf16(c0[0], c0[1], c0[2], c0[3],
                             ah[mf][0], ah[mf][1], ah[mf][2], ah[mf][3], bh0, bh1);
                    mma_bf16(c0[0], c0[1], c0[2], c0[3],
                             ah[mf][0], ah[mf][1], ah[mf][2], ah[mf][3], bl0, bl1);
                    mma_bf16(c0[0], c0[1], c0[2], c0[3],
                             al[mf][0], al[mf][1], al[mf][2], al[mf][3], bh0, bh1);
                    float* c1 = c[mf][2 * p + 1];
                    mma_bf16(c1[0], c1[1], c1[2], c1[3],
                             ah[mf][0], ah[mf][1], ah[mf][2], ah[mf][3], bh2, bh3);
                    mma_bf16(c1[0], c1[1], c1[2], c1[3],
                             ah[mf][0], ah[mf][1], ah[mf][2], ah[mf][3], bl2, bl3);
                    mma_bf16(c1[0], c1[1], c1[2], c1[3],
                             al[mf][0], al[mf][1], al[mf][2], al[mf][3], bh2, bh3);
                }
            }
        }
        __syncthreads();
    }

    // ---- epilogue: fp16 store + fused logits ----
    int head = (ctacol >> 6) + (warp_n >> 1);
    #pragma unroll
    for (int mf = 0; mf < 2; mf++) {
        int r0 = rowbase + warp_m * 32 + mf * 16 + (lane >> 2);
        int r1 = r0 + 8;
        float pes0 = 0.f, ped0 = 0.f, pes1 = 0.f, ped1 = 0.f;
        #pragma unroll
        for (int nf = 0; nf < 4; nf++) {
            int col = ctacol + warp_n * 32 + nf * 8 + (lane & 3) * 2;
            float av0 = __ldg(asrc + col), av1 = __ldg(asrc + col + 1);
            float dv0 = __ldg(adst + col), dv1 = __ldg(adst + col + 1);
            float* cc = c[mf][nf];
            pes0 += cc[0] * av0 + cc[1] * av1;
            ped0 += cc[0] * dv0 + cc[1] * dv1;
            pes1 += cc[2] * av0 + cc[3] * av1;
            ped1 += cc[2] * dv0 + cc[3] * dv1;
            if (r0 < NN)
                *(unsigned*)(out16 + (size_t)r0 * HH + col) = h2_as_u32(__floats2half2_rn(cc[0], cc[1]));
            if (r1 < NN)
                *(unsigned*)(out16 + (size_t)r1 * HH + col) = h2_as_u32(__floats2half2_rn(cc[2], cc[3]));
        }
        pes0 += __shfl_xor_sync(0xffffffffu, pes0, 1);
        pes0 += __shfl_xor_sync(0xffffffffu, pes0, 2);
        ped0 += __shfl_xor_sync(0xffffffffu, ped0, 1);
        ped0 += __shfl_xor_sync(0xffffffffu, ped0, 2);
        pes1 += __shfl_xor_sync(0xffffffffu, pes1, 1);
        pes1 += __shfl_xor_sync(0xffffffffu, pes1, 2);
        ped1 += __shfl_xor_sync(0xffffffffu, ped1, 1);
        ped1 += __shfl_xor_sync(0xffffffffu, ped1, 2);
        if ((lane & 3) == 0) {
            if (r0 < NN) {
                atomicAdd(&es[r0 * NHEAD + head], pes0);
                atomicAdd(&ed[r0 * NHEAD + head], ped0);
            }
            if (r1 < NN) {
                atomicAdd(&es[r1 * NHEAD + head], pes1);
                atomicAdd(&ed[r1 * NHEAD + head], ped1);
            }
        }
    }
}

// ---------------- per-head global max of es ----------------
__global__ void k_gmax(const float* __restrict__ es, unsigned* __restrict__ gmax) {
    __shared__ unsigned sm[NHEAD];
    int t = threadIdx.x;
    if (t < NHEAD) sm[t] = 0u;
    __syncthreads();
    float m0 = -1e30f, m1 = -1e30f, m2 = -1e30f, m3 = -1e30f;
    for (int n = blockIdx.x * blockDim.x + t; n < NN; n += gridDim.x * blockDim.x) {
        float4 v = ((const float4*)es)[n];
        m0 = fmaxf(m0, v.x); m1 = fmaxf(m1, v.y);
        m2 = fmaxf(m2, v.z); m3 = fmaxf(m3, v.w);
    }
    atomicMax(&sm[0], f_enc(m0));
    atomicMax(&sm[1], f_enc(m1));
    atomicMax(&sm[2], f_enc(m2));
    atomicMax(&sm[3], f_enc(m3));
    __syncthreads();
    if (t < NHEAD) atomicMax(&gmax[t], sm[t]);
}

// ---------------- aggregation: warp per dst node, global-shift softmax ----------------
__global__ void __launch_bounds__(256) k_agg(const __half* __restrict__ lin16,
                                             const float* __restrict__ bias,
                                             float* __restrict__ out,
                                             const float* __restrict__ es,
                                             const float* __restrict__ ed,
                                             const unsigned* __restrict__ gmax) {
    int n = (blockIdx.x * blockDim.x + threadIdx.x) >> 5;
    if (n >= NN) return;
    int lane = threadIdx.x & 31;

    int e0 = g_off[n], e1 = g_off[n + 1];
    float4 edv = ((const float4*)ed)[n];
    int head = lane >> 3;
    float edme = (head == 0) ? edv.x : (head == 1) ? edv.y : (head == 2) ? edv.z : edv.w;
    float mh = fmaxf(0.f, f_dec(__ldg(&gmax[head])) + edme);

    float a0=0,a1=0,a2=0,a3=0,a4=0,a5=0,a6=0,a7=0, den=0;
    const uint4* lp = (const uint4*)lin16;

    int e = e0;
    for (; e + 3 < e1; e += 4) {
        int s0 = g_csr_src[e];
        int s1 = g_csr_src[e + 1];
        int s2 = g_csr_src[e + 2];
        int s3 = g_csr_src[e + 3];
        float ex0 = __expf(lrelu(es[s0 * NHEAD + head] + edme) - mh);
        float ex1 = __expf(lrelu(es[s1 * NHEAD + head] + edme) - mh);
        float ex2 = __expf(lrelu(es[s2 * NHEAD + head] + edme) - mh);
        float ex3 = __expf(lrelu(es[s3 * NHEAD + head] + edme) - mh);
        uint4 r0 = lp[(size_t)s0 * 32 + lane];
        uint4 r1 = lp[(size_t)s1 * 32 + lane];
        uint4 r2 = lp[(size_t)s2 * 32 + lane];
        uint4 r3 = lp[(size_t)s3 * 32 + lane];
        den += (ex0 + ex1) + (ex2 + ex3);
        {
            float2 f0 = __half22float2(*(__half2*)&r0.x);
            float2 f1 = __half22float2(*(__half2*)&r0.y);
            float2 f2 = __half22float2(*(__half2*)&r0.z);
            float2 f3 = __half22float2(*(__half2*)&r0.w);
            a0 += ex0 * f0.x; a1 += ex0 * f0.y; a2 += ex0 * f1.x; a3 += ex0 * f1.y;
            a4 += ex0 * f2.x; a5 += ex0 * f2.y; a6 += ex0 * f3.x; a7 += ex0 * f3.y;
        }
        {
            float2 f0 = __half22float2(*(__half2*)&r1.x);
            float2 f1 = __half22float2(*(__half2*)&r1.y);
            float2 f2 = __half22float2(*(__half2*)&r1.z);
            float2 f3 = __half22float2(*(__half2*)&r1.w);
            a0 += ex1 * f0.x; a1 += ex1 * f0.y; a2 += ex1 * f1.x; a3 += ex1 * f1.y;
            a4 += ex1 * f2.x; a5 += ex1 * f2.y; a6 += ex1 * f3.x; a7 += ex1 * f3.y;
        }
        {
            float2 f0 = __half22float2(*(__half2*)&r2.x);
            float2 f1 = __half22float2(*(__half2*)&r2.y);
            float2 f2 = __half22float2(*(__half2*)&r2.z);
            float2 f3 = __half22float2(*(__half2*)&r2.w);
            a0 += ex2 * f0.x; a1 += ex2 * f0.y; a2 += ex2 * f1.x; a3 += ex2 * f1.y;
            a4 += ex2 * f2.x; a5 += ex2 * f2.y; a6 += ex2 * f3.x; a7 += ex2 * f3.y;
        }
        {
            float2 f0 = __half22float2(*(__half2*)&r3.x);
            float2 f1 = __half22float2(*(__half2*)&r3.y);
            float2 f2 = __half22float2(*(__half2*)&r3.z);
            float2 f3 = __half22float2(*(__half2*)&r3.w);
            a0 += ex3 * f0.x; a1 += ex3 * f0.y; a2 += ex3 * f1.x; a3 += ex3 * f1.y;
            a4 += ex3 * f2.x; a5 += ex3 * f2.y; a6 += ex3 * f3.x; a7 += ex3 * f3.y;
        }
    }
    for (; e < e1; e++) {
        int s0 = g_csr_src[e];
        float ex0 = __expf(lrelu(es[s0 * NHEAD + head] + edme) - mh);
        uint4 r0 = lp[(size_t)s0 * 32 + lane];
        den += ex0;
        float2 f0 = __half22float2(*(__half2*)&r0.x);
        float2 f1 = __half22float2(*(__half2*)&r0.y);
        float2 f2 = __half22float2(*(__half2*)&r0.z);
        float2 f3 = __half22float2(*(__half2*)&r0.w);
        a0 += ex0 * f0.x; a1 += ex0 * f0.y; a2 += ex0 * f1.x; a3 += ex0 * f1.y;
        a4 += ex0 * f2.x; a5 += ex0 * f2.y; a6 += ex0 * f3.x; a7 += ex0 * f3.y;
    }

    float inv = 1.f / (den + 1e-16f);
    const float4* bv = (const float4*)(bias + lane * 8);
    float4 bb0 = __ldg(&bv[0]), bb1 = __ldg(&bv[1]);
    float4 o0, o1;
    o0.x = fmaxf(a0 * inv + bb0.x, 0.f);
    o0.y = fmaxf(a1 * inv + bb0.y, 0.f);
    o0.z = fmaxf(a2 * inv + bb0.z, 0.f);
    o0.w = fmaxf(a3 * inv + bb0.w, 0.f);
    o1.x = fmaxf(a4 * inv + bb1.x, 0.f);
    o1.y = fmaxf(a5 * inv + bb1.y, 0.f);
    o1.z = fmaxf(a6 * inv + bb1.z, 0.f);
    o1.w = fmaxf(a7 * inv + bb1.w, 0.f);
    ((float4*)(out + (size_t)n * HH))[lane * 2]     = o0;
    ((float4*)(out + (size_t)n * HH))[lane * 2 + 1] = o1;
}

// ---------------- pooling ----------------
__global__ void __launch_bounds__(640) k_pool(const float* __restrict__ x,
                                              const int* __restrict__ batch) {
    __shared__ int bsh[256];
    int t = threadIdx.x;
    int n0 = blockIdx.x * 256;
    int cnt = min(256, NN - n0);
    for (int i = t; i < cnt; i += 640) bsh[i] = batch[n0 + i];
    __syncthreads();

    const float* base; int stride, coff;
    if (t < 128)      { base = x;    stride = INCH; coff = t;       }
    else if (t < 384) { base = g_h1; stride = HH;   coff = t - 128; }
    else              { base = g_h2; stride = HH;   coff = t - 384; }

    float acc = 0.f;
    int curg = bsh[0];
    #pragma unroll 4
    for (int i = 0; i < cnt; i++) {
        int g = bsh[i];
        float v = base[(size_t)(n0 + i) * stride + coff];
        if (g != curg) {
            atomicAdd(&g_pool[curg * DCAT + t], acc);
            acc = 0.f;
            curg = g;
        }
        acc += v;
    }
    atomicAdd(&g_pool[curg * DCAT + t], acc);
}

// ---------------- final MLP ----------------
__global__ void k_mlp(const float* __restrict__ W3, const float* __restrict__ b3,
                      const float* __restrict__ W4, const float* __restrict__ b4,
                      float* __restrict__ out) {
    int g = blockIdx.x;
    int t = threadIdx.x;
    __shared__ float p[DCAT];
    __shared__ float hm[256];
    float invc = 1.f / fmaxf(g_cnt[g], 1.f);
    for (int i = t; i < DCAT; i += 256) p[i] = g_pool[g * DCAT + i] * invc;
    __syncthreads();
    float acc = b3[t];
    for (int k = 0; k < DCAT; k++) acc += p[k] * W3[k * 256 + t];
    hm[t] = fmaxf(acc, 0.f);
    __syncthreads();
    if (t < 128) {
        float a2 = b4[t];
        for (int k = 0; k < 256; k++) a2 += hm[k] * W4[k * 128 + t];
        out[g * 128 + t] = a2;
    }
}

// ---------------- launch ----------------
extern "C" void kernel_launch(void* const* d_in, const int* in_sizes, int n_in,
                              void* d_out, int out_size) {
    const float* x     = (const float*)d_in[0];
    const int*   ei    = (const int*)d_in[1];
    const int*   batch = (const int*)d_in[2];
    const float* W1  = (const float*)d_in[3];
    const float* a1s = (const float*)d_in[4];
    const float* a1d = (const float*)d_in[5];
    const float* b1  = (const float*)d_in[6];
    const float* W2  = (const float*)d_in[7];
    const float* a2s = (const float*)d_in[8];
    const float* a2d = (const float*)d_in[9];
    const float* b2  = (const float*)d_in[10];
    const float* W3  = (const float*)d_in[11];
    const float* b3  = (const float*)d_in[12];
    const float* W4  = (const float*)d_in[13];
    const float* b4  = (const float*)d_in[14];
    float* out = (float*)d_out;

    void *p_l16, *p_h1, *p_h2;
    void *p_esA, *p_edA, *p_esB, *p_edB, *p_gmA, *p_gmB;
    void *p_wh1, *p_wl1, *p_wh2, *p_wl2;
    cudaGetSymbolAddress(&p_l16, g_lin16);
    cudaGetSymbolAddress(&p_h1,  g_h1);
    cudaGetSymbolAddress(&p_h2,  g_h2);
    cudaGetSymbolAddress(&p_esA, g_esA);
    cudaGetSymbolAddress(&p_edA, g_edA);
    cudaGetSymbolAddress(&p_esB, g_esB);
    cudaGetSymbolAddress(&p_edB, g_edB);
    cudaGetSymbolAddress(&p_gmA, g_gmaxA);
    cudaGetSymbolAddress(&p_gmB, g_gmaxB);
    cudaGetSymbolAddress(&p_wh1, g_wbh1);
    cudaGetSymbolAddress(&p_wl1, g_wbl1);
    cudaGetSymbolAddress(&p_wh2, g_wbh2);
    cudaGetSymbolAddress(&p_wl2, g_wbl2);
    __half* lin16 = (__half*)p_l16;
    float*  h1    = (float*)p_h1;
    float*  h2    = (float*)p_h2;

    const int SMEM_GEMM = (2 * 64 * KP + 2 * 128 * KP) * sizeof(__nv_bfloat16);  // 55,296 B
    cudaFuncSetAttribute(k_gemm_tc<128>, cudaFuncAttributeMaxDynamicSharedMemorySize, SMEM_GEMM);
    cudaFuncSetAttribute(k_gemm_tc<256>, cudaFuncAttributeMaxDynamicSharedMemorySize, SMEM_GEMM);

    dim3 gemm_grid((NN + 63) / 64, 2);
    int warp_blocks = (NN * 32 + 255) / 256;
    dim3 tb(32, 8);

    // slot 4 = gemm<128> (profiled)
    k_split_w<<<dim3(8, 8, 2), tb>>>(W1, W2);                      // 1
    k_zero<<<(NN + 255) / 256, 256>>>();                           // 2
    k_hist<<<(NE + 255) / 256, 256>>>(ei, batch);                  // 3
    k_gemm_tc<128><<<gemm_grid, 256, SMEM_GEMM>>>(                 // 4 <- profiled
        x, (__nv_bfloat16*)p_wh1, (__nv_bfloat16*)p_wl1,
        lin16, a1s, a1d, (float*)p_esA, (float*)p_edA);
    k_scan<<<1, 1024>>>();                                         // 5
    k_scatter<<<(NE + 255) / 256, 256>>>(ei);                      // 6
    k_gmax<<<160, 256>>>((const float*)p_esA, (unsigned*)p_gmA);   // 7

    k_agg<<<warp_blocks, 256>>>(lin16, b1, h1,
        (const float*)p_esA, (const float*)p_edA, (const unsigned*)p_gmA);

    k_gemm_tc<256><<<gemm_grid, 256, SMEM_GEMM>>>(
        h1, (__nv_bfloat16*)p_wh2, (__nv_bfloat16*)p_wl2,
        lin16, a2s, a2d, (float*)p_esB, (float*)p_edB);
    k_gmax<<<160, 256>>>((const float*)p_esB, (unsigned*)p_gmB);
    k_agg<<<warp_blocks, 256>>>(lin16, b2, h2,
        (const float*)p_esB, (const float*)p_edB, (const unsigned*)p_gmB);

    k_pool<<<(NN + 255) / 256, 640>>>(x, batch);
    k_mlp<<<GG, 256>>>(W3, b3, W4, b4, out);
}